// round 5
// baseline (speedup 1.0000x reference)
#include <cuda_runtime.h>
#include <math.h>
#include <stdint.h>

#define HIDDEN 2048
#define NH     32
#define NKV    4
#define HD     128
#define BB     2
#define SS     2048
#define QKV_O  ((NH + 2*NKV)*HD)   /* 5120 */
#define MTOK   (BB*SS)             /* 4096 */
#define SCALE  0.08838834764831845f /* 1/sqrt(128) */

/* ---------------- scratch ---------------- */
__device__ float g_qkv[(size_t)MTOK * QKV_O];
__device__ float g_q[(size_t)BB * NH * SS * HD];
__device__ float g_k[(size_t)BB * NKV * SS * HD];
__device__ float g_v[(size_t)BB * NKV * SS * HD];
__device__ float g_attn[(size_t)MTOK * NH * HD];

/* ---------------- helpers ---------------- */
__device__ __forceinline__ uint32_t f2tf32(float x) {
    uint32_t r;
    asm("cvt.rna.tf32.f32 %0, %1;" : "=r"(r) : "f"(x));
    return r;
}

__device__ __forceinline__ void mma_tf32(float* c,
    uint32_t a0, uint32_t a1, uint32_t a2, uint32_t a3,
    uint32_t b0, uint32_t b1)
{
    asm volatile(
        "mma.sync.aligned.m16n8k8.row.col.f32.tf32.tf32.f32 "
        "{%0,%1,%2,%3}, {%4,%5,%6,%7}, {%8,%9}, {%0,%1,%2,%3};"
        : "+f"(c[0]), "+f"(c[1]), "+f"(c[2]), "+f"(c[3])
        : "r"(a0), "r"(a1), "r"(a2), "r"(a3), "r"(b0), "r"(b1));
}

__device__ __forceinline__ void cp16(void* smem, const void* g) {
    uint32_t s = (uint32_t)__cvta_generic_to_shared(smem);
    asm volatile("cp.async.ca.shared.global [%0], [%1], 16;" :: "r"(s), "l"(g));
}
__device__ __forceinline__ void cp_commit() {
    asm volatile("cp.async.commit_group;" ::: "memory");
}
__device__ __forceinline__ void cp_wait0() {
    asm volatile("cp.async.wait_group 0;" ::: "memory");
}
__device__ __forceinline__ void cp_wait1() {
    asm volatile("cp.async.wait_group 1;" ::: "memory");
}

/* ---------------- tf32 GEMM, cp.async 2-stage, 2 CTA/SM (unchanged R4) ---- */
#define GSTG   4608
#define G_SMEM (4 * GSTG * 4)

__global__ __launch_bounds__(256, 2) void gemm_tf32(
    const float* __restrict__ A, const float* __restrict__ B,
    float* __restrict__ C, int M, int N, int K)
{
    extern __shared__ float smf[];
    const int tid  = threadIdx.x;
    const int lane = tid & 31, wid = tid >> 5;
    const int g = lane >> 2, t = lane & 3;
    const int wm = (wid & 1) << 6;
    const int wn = (wid >> 1) << 5;
    const int m0 = blockIdx.y << 7, n0 = blockIdx.x << 7;

    const int r0 = tid >> 3;
    const int c0 = (tid & 7) << 2;

    float acc[4][4][4];
#pragma unroll
    for (int mt = 0; mt < 4; ++mt)
#pragma unroll
        for (int nt = 0; nt < 4; ++nt)
#pragma unroll
            for (int i = 0; i < 4; ++i) acc[mt][nt][i] = 0.0f;

    const int T = K >> 5;

#pragma unroll
    for (int p = 0; p < 4; ++p) {
        int rr = r0 + 32 * p;
        cp16(smf + rr * 36 + c0,            A + (size_t)(m0 + rr) * K + c0);
        cp16(smf + 2*GSTG + rr * 36 + c0,   B + (size_t)(n0 + rr) * K + c0);
    }
    cp_commit();

    for (int kt = 0; kt < T; ++kt) {
        const int s = kt & 1;
        cp_wait0();
        __syncthreads();

        if (kt + 1 < T) {
            const int s2 = (kt + 1) & 1;
            const int k0 = (kt + 1) << 5;
#pragma unroll
            for (int p = 0; p < 4; ++p) {
                int rr = r0 + 32 * p;
                cp16(smf + s2 * GSTG + rr * 36 + c0,
                     A + (size_t)(m0 + rr) * K + k0 + c0);
                cp16(smf + 2*GSTG + s2 * GSTG + rr * 36 + c0,
                     B + (size_t)(n0 + rr) * K + k0 + c0);
            }
            cp_commit();
        }

        const float* As = smf + s * GSTG;
        const float* Bs = smf + 2*GSTG + s * GSTG;
#pragma unroll
        for (int kk = 0; kk < 4; ++kk) {
            const int kb = kk << 3;
            uint32_t af[4][4], bf[4][2];
#pragma unroll
            for (int mt = 0; mt < 4; ++mt) {
                int row = wm + (mt << 4) + g;
                af[mt][0] = f2tf32(As[row * 36 + kb + t]);
                af[mt][1] = f2tf32(As[(row + 8) * 36 + kb + t]);
                af[mt][2] = f2tf32(As[row * 36 + kb + t + 4]);
                af[mt][3] = f2tf32(As[(row + 8) * 36 + kb + t + 4]);
            }
#pragma unroll
            for (int nt = 0; nt < 4; ++nt) {
                int row = wn + (nt << 3) + g;
                bf[nt][0] = f2tf32(Bs[row * 36 + kb + t]);
                bf[nt][1] = f2tf32(Bs[row * 36 + kb + t + 4]);
            }
#pragma unroll
            for (int mt = 0; mt < 4; ++mt)
#pragma unroll
                for (int nt = 0; nt < 4; ++nt)
                    mma_tf32(acc[mt][nt],
                             af[mt][0], af[mt][1], af[mt][2], af[mt][3],
                             bf[nt][0], bf[nt][1]);
        }
    }

#pragma unroll
    for (int mt = 0; mt < 4; ++mt) {
        int row = m0 + wm + (mt << 4) + g;
#pragma unroll
        for (int nt = 0; nt < 4; ++nt) {
            int col = n0 + wn + (nt << 3) + (t << 1);
            float2 v0; v0.x = acc[mt][nt][0]; v0.y = acc[mt][nt][1];
            float2 v1; v1.x = acc[mt][nt][2]; v1.y = acc[mt][nt][3];
            *(float2*)(C + (size_t)row * N + col)       = v0;
            *(float2*)(C + (size_t)(row + 8) * N + col) = v1;
        }
    }
}

/* ---------------- per-head RMSNorm + RoPE + scatter (unchanged) ------------ */
__global__ void norm_rope(
    const float* __restrict__ qkv, const int* __restrict__ pos,
    const float* __restrict__ qw, const float* __restrict__ kw,
    float* __restrict__ qo, float* __restrict__ ko, float* __restrict__ vo)
{
    const int slot = blockIdx.x, s = blockIdx.y, b = blockIdx.z;
    const int d = threadIdx.x;
    const size_t token = (size_t)b * SS + s;
    float x = qkv[token * QKV_O + (size_t)slot * HD + d];

    if (slot >= 36) {
        vo[(((size_t)b * NKV + (slot - 36)) * SS + s) * HD + d] = x;
        return;
    }

    __shared__ float red[4];
    __shared__ float xs[HD];
    __shared__ float rstd;

    float ssq = x * x;
#pragma unroll
    for (int o = 16; o; o >>= 1) ssq += __shfl_xor_sync(0xffffffffu, ssq, o);
    if ((d & 31) == 0) red[d >> 5] = ssq;
    __syncthreads();
    if (d == 0) rstd = rsqrtf((red[0] + red[1] + red[2] + red[3]) * (1.0f / HD) + 1e-6f);
    __syncthreads();

    float w = (slot < 32) ? qw[d] : kw[d];
    float xn = x * rstd * w;
    xs[d] = xn;
    __syncthreads();

    int p = pos[token];
    int j = d & 63;
    float invf = expf((float)j * (-13.815510557964274f / 64.0f));
    float ang = (float)p * invf;
    float sn, cs;
    sincosf(ang, &sn, &cs);
    float out = (d < 64) ? (xn * cs - xs[d + 64] * sn)
                         : (xn * cs + xs[d - 64] * sn);

    if (slot < 32) qo[(((size_t)b * NH + slot) * SS + s) * HD + d] = out;
    else           ko[(((size_t)b * NKV + (slot - 32)) * SS + s) * HD + d] = out;
}

/* ---------------- flash attention: FBQ=128, cp.async 2-stage, swizzled ------
   8 warps (256 thr); warp w owns Q rows [16w,16w+16) of the 128-row tile.
   Smem (words): Q 128x128 (tf32, swz (r&7)<<2), K 2x64x128 raw fp32
   (swz (r&7)<<2), V 2x64x128 raw fp32 (swz (r&3)<<3), P 8x16x64 tf32
   (swz (r&7)<<2).  Total 57344 words = 229376 B -> 1 CTA/SM. */
#define FBQ  128
#define FBK  64
#define QW   16384
#define KW   8192
#define VW   8192
#define PW   1024
#define FTC_SMEM ((QW + 2*KW + 2*VW + 8*PW) * 4)   /* 229376 */

__global__ __launch_bounds__(256, 1) void flash_tc(
    const float* __restrict__ Qb, const float* __restrict__ Kb,
    const float* __restrict__ Vb, float* __restrict__ Ob)
{
    extern __shared__ uint32_t su[];
    uint32_t* Qs  = su;                 /* tf32 */
    uint32_t* Kst = su + QW;            /* 2 stages raw fp32 */
    uint32_t* Vst = su + QW + 2*KW;     /* 2 stages raw fp32 */
    uint32_t* Ps  = su + QW + 2*KW + 2*VW;

    const int tid = threadIdx.x;
    const int lane = tid & 31, w = tid >> 5;
    const int g = lane >> 2, t = lane & 3;
    const int qt = (gridDim.x - 1) - blockIdx.x;   /* heaviest first */
    const int h = blockIdx.y, b = blockIdx.z;
    const int q0 = qt * FBQ;
    const int kh = h >> 3;

    const float* Qg  = Qb + (((size_t)b * NH + h) * SS + q0) * HD;
    const float* Kg0 = Kb + ((size_t)b * NKV + kh) * SS * HD;
    const float* Vg0 = Vb + ((size_t)b * NKV + kh) * SS * HD;

    const int ntiles = 2 * qt + 2;

    /* issue stage 0 K/V cp.async (8 float4 per thread per matrix) */
    {
        const float* Kg = Kg0;
        const float* Vg = Vg0;
#pragma unroll
        for (int i = 0; i < 8; ++i) {
            int f = tid + (i << 8);
            int r = f >> 5, c4 = (f & 31) << 2;
            cp16(Kst + r * 128 + (c4 ^ ((r & 7) << 2)), Kg + (size_t)r * HD + c4);
            cp16(Vst + r * 128 + (c4 ^ ((r & 3) << 3)), Vg + (size_t)r * HD + c4);
        }
        cp_commit();
    }

    /* stage Q tile (scaled, tf32, swizzled) — overlaps stage-0 cp.async */
#pragma unroll
    for (int i = 0; i < 16; ++i) {
        int f = tid + (i << 8);
        int r = f >> 5, c4 = (f & 31) << 2;
        float4 v = *(const float4*)(Qg + (size_t)r * HD + c4);
        uint4 u;
        u.x = f2tf32(v.x * SCALE); u.y = f2tf32(v.y * SCALE);
        u.z = f2tf32(v.z * SCALE); u.w = f2tf32(v.w * SCALE);
        *(uint4*)&Qs[r * 128 + (c4 ^ ((r & 7) << 2))] = u;
    }

    float o[16][4];
#pragma unroll
    for (int dt = 0; dt < 16; ++dt)
#pragma unroll
        for (int i = 0; i < 4; ++i) o[dt][i] = 0.0f;
    float mr0 = -1e30f, mr1 = -1e30f, lr0 = 0.0f, lr1 = 0.0f;

    uint32_t* Pw = Ps + w * PW;
    const int qrow0 = q0 + w * 16 + g;
    const int sw_g = g << 2;   /* row-pattern swizzle term */

    for (int tt = 0; tt < ntiles; ++tt) {
        const int s = tt & 1;

        /* issue next stage into buffer s^1 (its readers sync'd last iter) */
        if (tt + 1 < ntiles) {
            const float* Kg = Kg0 + (size_t)(tt + 1) * FBK * HD;
            const float* Vg = Vg0 + (size_t)(tt + 1) * FBK * HD;
            uint32_t* Kd = Kst + (s ^ 1) * KW;
            uint32_t* Vd = Vst + (s ^ 1) * VW;
#pragma unroll
            for (int i = 0; i < 8; ++i) {
                int f = tid + (i << 8);
                int r = f >> 5, c4 = (f & 31) << 2;
                cp16(Kd + r * 128 + (c4 ^ ((r & 7) << 2)), Kg + (size_t)r * HD + c4);
                cp16(Vd + r * 128 + (c4 ^ ((r & 3) << 3)), Vg + (size_t)r * HD + c4);
            }
            cp_commit();
            cp_wait1();
        } else {
            cp_wait0();
        }
        __syncthreads();     /* stage s ready (also orders Q writes on tt=0) */

        const uint32_t* Kf = Kst + s * KW;
        const uint32_t* Vf = Vst + s * VW;

        /* S = Q K^T */
        float sc[8][4];
#pragma unroll
        for (int nt = 0; nt < 8; ++nt)
#pragma unroll
            for (int i = 0; i < 4; ++i) sc[nt][i] = 0.0f;

#pragma unroll
        for (int ks = 0; ks < 16; ++ks) {
            const int kb = ks << 3;
            const int cA = (kb + t) ^ sw_g;
            const int cB = (kb + t + 4) ^ sw_g;
            const int qr = (w * 16 + g) * 128;
            uint32_t a0 = Qs[qr + cA];
            uint32_t a1 = Qs[qr + 8 * 128 + cA];
            uint32_t a2 = Qs[qr + cB];
            uint32_t a3 = Qs[qr + 8 * 128 + cB];
#pragma unroll
            for (int nt = 0; nt < 8; ++nt) {
                uint32_t b0 = f2tf32(__uint_as_float(Kf[(nt * 8 + g) * 128 + cA]));
                uint32_t b1 = f2tf32(__uint_as_float(Kf[(nt * 8 + g) * 128 + cB]));
                mma_tf32(sc[nt], a0, a1, a2, a3, b0, b1);
            }
        }

        /* causal mask: last two k-tiles touch the diagonal */
        if (tt >= ntiles - 2) {
            const int k0g = tt * FBK + 2 * t;
#pragma unroll
            for (int nt = 0; nt < 8; ++nt) {
                int kc = k0g + nt * 8;
                if (kc     > qrow0)     sc[nt][0] = -1e30f;
                if (kc + 1 > qrow0)     sc[nt][1] = -1e30f;
                if (kc     > qrow0 + 8) sc[nt][2] = -1e30f;
                if (kc + 1 > qrow0 + 8) sc[nt][3] = -1e30f;
            }
        }

        /* online softmax (rows qrow0, qrow0+8); quad shfl reduce */
        float m0 = -1e30f, m1 = -1e30f;
#pragma unroll
        for (int nt = 0; nt < 8; ++nt) {
            m0 = fmaxf(m0, fmaxf(sc[nt][0], sc[nt][1]));
            m1 = fmaxf(m1, fmaxf(sc[nt][2], sc[nt][3]));
        }
        m0 = fmaxf(m0, __shfl_xor_sync(0xffffffffu, m0, 1));
        m0 = fmaxf(m0, __shfl_xor_sync(0xffffffffu, m0, 2));
        m1 = fmaxf(m1, __shfl_xor_sync(0xffffffffu, m1, 1));
        m1 = fmaxf(m1, __shfl_xor_sync(0xffffffffu, m1, 2));
        float mn0 = fmaxf(mr0, m0), mn1 = fmaxf(mr1, m1);
        float a0r = __expf(mr0 - mn0), a1r = __expf(mr1 - mn1);
        float s0 = 0.0f, s1 = 0.0f;
#pragma unroll
        for (int nt = 0; nt < 8; ++nt) {
            sc[nt][0] = __expf(sc[nt][0] - mn0); s0 += sc[nt][0];
            sc[nt][1] = __expf(sc[nt][1] - mn0); s0 += sc[nt][1];
            sc[nt][2] = __expf(sc[nt][2] - mn1); s1 += sc[nt][2];
            sc[nt][3] = __expf(sc[nt][3] - mn1); s1 += sc[nt][3];
        }
        s0 += __shfl_xor_sync(0xffffffffu, s0, 1);
        s0 += __shfl_xor_sync(0xffffffffu, s0, 2);
        s1 += __shfl_xor_sync(0xffffffffu, s1, 1);
        s1 += __shfl_xor_sync(0xffffffffu, s1, 2);
        lr0 = lr0 * a0r + s0; mr0 = mn0;
        lr1 = lr1 * a1r + s1; mr1 = mn1;
#pragma unroll
        for (int dt = 0; dt < 16; ++dt) {
            o[dt][0] *= a0r; o[dt][1] *= a0r;
            o[dt][2] *= a1r; o[dt][3] *= a1r;
        }

        /* P -> per-warp smem (tf32, 16x64 swizzled) */
#pragma unroll
        for (int nt = 0; nt < 8; ++nt) {
            int c = nt * 8 + 2 * t;
            int cw = c ^ sw_g;
            Pw[g * 64 + cw]           = f2tf32(sc[nt][0]);
            Pw[g * 64 + cw + 1]       = f2tf32(sc[nt][1]);
            Pw[(g + 8) * 64 + cw]     = f2tf32(sc[nt][2]);
            Pw[(g + 8) * 64 + cw + 1] = f2tf32(sc[nt][3]);
        }
        __syncwarp();

        /* O += P V */
#pragma unroll
        for (int ks = 0; ks < 8; ++ks) {
            const int kb = ks << 3;
            const int cA = (kb + t) ^ sw_g;
            const int cB = (kb + t + 4) ^ sw_g;
            uint32_t a0 = Pw[g * 64 + cA];
            uint32_t a1 = Pw[(g + 8) * 64 + cA];
            uint32_t a2 = Pw[g * 64 + cB];
            uint32_t a3 = Pw[(g + 8) * 64 + cB];
            const int vr0 = (kb + t) * 128;
            const int vr1 = (kb + t + 4) * 128;
            const int vsw = t << 3;
#pragma unroll
            for (int dt = 0; dt < 16; ++dt) {
                int vc = (dt * 8 + g) ^ vsw;
                uint32_t b0 = f2tf32(__uint_as_float(Vf[vr0 + vc]));
                uint32_t b1 = f2tf32(__uint_as_float(Vf[vr1 + vc]));
                mma_tf32(o[dt], a0, a1, a2, a3, b0, b1);
            }
        }
        __syncthreads();   /* all reads of stage s done before next overwrite */
    }

    /* epilogue -> [b][s][h][d] */
    const float inv0 = 1.0f / lr0, inv1 = 1.0f / lr1;
    const size_t base0 = (((size_t)b * SS + qrow0) * NH + h) * HD;
    const size_t base1 = (((size_t)b * SS + qrow0 + 8) * NH + h) * HD;
#pragma unroll
    for (int dt = 0; dt < 16; ++dt) {
        int col = dt * 8 + 2 * t;
        float2 v0; v0.x = o[dt][0] * inv0; v0.y = o[dt][1] * inv0;
        float2 v1; v1.x = o[dt][2] * inv1; v1.y = o[dt][3] * inv1;
        *(float2*)(Ob + base0 + col) = v0;
        *(float2*)(Ob + base1 + col) = v1;
    }
}

/* ---------------- launch ---------------- */
extern "C" void kernel_launch(void* const* d_in, const int* in_sizes, int n_in,
                              void* d_out, int out_size)
{
    const float* hidden    = (const float*)d_in[0];
    const int*   positions = (const int*)d_in[1];
    const float* w_qkv     = (const float*)d_in[2];
    const float* w_o       = (const float*)d_in[3];
    const float* qw        = (const float*)d_in[4];
    const float* kw        = (const float*)d_in[5];
    float* out = (float*)d_out;

    float *qkv, *qb, *kb, *vb, *ab;
    cudaGetSymbolAddress((void**)&qkv, g_qkv);
    cudaGetSymbolAddress((void**)&qb,  g_q);
    cudaGetSymbolAddress((void**)&kb,  g_k);
    cudaGetSymbolAddress((void**)&vb,  g_v);
    cudaGetSymbolAddress((void**)&ab,  g_attn);

    cudaFuncSetAttribute(gemm_tf32, cudaFuncAttributeMaxDynamicSharedMemorySize, G_SMEM);
    cudaFuncSetAttribute(flash_tc, cudaFuncAttributeMaxDynamicSharedMemorySize, FTC_SMEM);

    gemm_tf32<<<dim3(QKV_O / 128, MTOK / 128), 256, G_SMEM>>>(hidden, w_qkv, qkv, MTOK, QKV_O, HIDDEN);

    norm_rope<<<dim3(40, SS, BB), 128>>>(qkv, positions, qw, kw, qb, kb, vb);

    flash_tc<<<dim3(SS / FBQ, NH, BB), 256, FTC_SMEM>>>(qb, kb, vb, ab);

    gemm_tf32<<<dim3(HIDDEN / 128, MTOK / 128), 256, G_SMEM>>>(ab, w_o, out, MTOK, HIDDEN, NH * HD);
}

// round 8
// speedup vs baseline: 1.1550x; 1.1550x over previous
#include <cuda_runtime.h>
#include <math.h>
#include <stdint.h>

#define HIDDEN 2048
#define NH     32
#define NKV    4
#define HD     128
#define BB     2
#define SS     2048
#define QKV_O  ((NH + 2*NKV)*HD)   /* 5120 */
#define MTOK   (BB*SS)             /* 4096 */
#define SCALE  0.08838834764831845f /* 1/sqrt(128) */

/* ---------------- scratch ---------------- */
__device__ float g_qkv[(size_t)MTOK * QKV_O];
__device__ float g_q[(size_t)BB * NH * SS * HD];
__device__ float g_k[(size_t)BB * NKV * SS * HD];
__device__ float g_v[(size_t)BB * NKV * SS * HD];
__device__ float g_attn[(size_t)MTOK * NH * HD];
__device__ float g_hid[(size_t)MTOK * HIDDEN];      /* tf32-rounded hidden  */
__device__ float g_wq[(size_t)QKV_O * HIDDEN];      /* tf32-rounded w_qkv   */
__device__ float g_wo[(size_t)HIDDEN * NH * HD];    /* tf32-rounded w_o     */

/* ---------------- helpers ---------------- */
__device__ __forceinline__ uint32_t f2tf32(float x) {
    uint32_t r;
    asm("cvt.rna.tf32.f32 %0, %1;" : "=r"(r) : "f"(x));
    return r;
}
__device__ __forceinline__ float rtf(float x) { return __uint_as_float(f2tf32(x)); }

__device__ __forceinline__ void mma_tf32(float* c,
    uint32_t a0, uint32_t a1, uint32_t a2, uint32_t a3,
    uint32_t b0, uint32_t b1)
{
    asm volatile(
        "mma.sync.aligned.m16n8k8.row.col.f32.tf32.tf32.f32 "
        "{%0,%1,%2,%3}, {%4,%5,%6,%7}, {%8,%9}, {%0,%1,%2,%3};"
        : "+f"(c[0]), "+f"(c[1]), "+f"(c[2]), "+f"(c[3])
        : "r"(a0), "r"(a1), "r"(a2), "r"(a3), "r"(b0), "r"(b1));
}

__device__ __forceinline__ void cp16(void* smem, const void* g) {
    uint32_t s = (uint32_t)__cvta_generic_to_shared(smem);
    asm volatile("cp.async.ca.shared.global [%0], [%1], 16;" :: "r"(s), "l"(g));
}
__device__ __forceinline__ void cp_commit() {
    asm volatile("cp.async.commit_group;" ::: "memory");
}
__device__ __forceinline__ void cp_wait0() {
    asm volatile("cp.async.wait_group 0;" ::: "memory");
}

/* ---------------- tf32 pre-rounding pass ---------------- */
__global__ void round_tf32(const float4* __restrict__ s, float4* __restrict__ d, int n4)
{
    int i = blockIdx.x * blockDim.x + threadIdx.x;
    if (i < n4) {
        float4 v = s[i];
        v.x = rtf(v.x); v.y = rtf(v.y); v.z = rtf(v.z); v.w = rtf(v.w);
        d[i] = v;
    }
}

/* ---------------- tf32 GEMM, cp.async 2-stage, 2 CTA/SM, no in-loop cvt ---- */
#define GSTG   4608
#define G_SMEM (4 * GSTG * 4)

__global__ __launch_bounds__(256, 2) void gemm_tf32(
    const float* __restrict__ A, const float* __restrict__ B,
    float* __restrict__ C, int M, int N, int K)
{
    extern __shared__ float smf[];
    const int tid  = threadIdx.x;
    const int lane = tid & 31, wid = tid >> 5;
    const int g = lane >> 2, t = lane & 3;
    const int wm = (wid & 1) << 6;
    const int wn = (wid >> 1) << 5;
    const int m0 = blockIdx.y << 7, n0 = blockIdx.x << 7;

    const int r0 = tid >> 3;
    const int c0 = (tid & 7) << 2;

    float acc[4][4][4];
#pragma unroll
    for (int mt = 0; mt < 4; ++mt)
#pragma unroll
        for (int nt = 0; nt < 4; ++nt)
#pragma unroll
            for (int i = 0; i < 4; ++i) acc[mt][nt][i] = 0.0f;

    const int T = K >> 5;

#pragma unroll
    for (int p = 0; p < 4; ++p) {
        int rr = r0 + 32 * p;
        cp16(smf + rr * 36 + c0,            A + (size_t)(m0 + rr) * K + c0);
        cp16(smf + 2*GSTG + rr * 36 + c0,   B + (size_t)(n0 + rr) * K + c0);
    }
    cp_commit();

    for (int kt = 0; kt < T; ++kt) {
        const int s = kt & 1;
        cp_wait0();
        __syncthreads();

        if (kt + 1 < T) {
            const int s2 = (kt + 1) & 1;
            const int k0 = (kt + 1) << 5;
#pragma unroll
            for (int p = 0; p < 4; ++p) {
                int rr = r0 + 32 * p;
                cp16(smf + s2 * GSTG + rr * 36 + c0,
                     A + (size_t)(m0 + rr) * K + k0 + c0);
                cp16(smf + 2*GSTG + s2 * GSTG + rr * 36 + c0,
                     B + (size_t)(n0 + rr) * K + k0 + c0);
            }
            cp_commit();
        }

        const uint32_t* As = (const uint32_t*)(smf + s * GSTG);
        const uint32_t* Bs = (const uint32_t*)(smf + 2*GSTG + s * GSTG);
#pragma unroll
        for (int kk = 0; kk < 4; ++kk) {
            const int kb = kk << 3;
            uint32_t af[4][4], bf[4][2];
#pragma unroll
            for (int mt = 0; mt < 4; ++mt) {
                int row = wm + (mt << 4) + g;
                af[mt][0] = As[row * 36 + kb + t];
                af[mt][1] = As[(row + 8) * 36 + kb + t];
                af[mt][2] = As[row * 36 + kb + t + 4];
                af[mt][3] = As[(row + 8) * 36 + kb + t + 4];
            }
#pragma unroll
            for (int nt = 0; nt < 4; ++nt) {
                int row = wn + (nt << 3) + g;
                bf[nt][0] = Bs[row * 36 + kb + t];
                bf[nt][1] = Bs[row * 36 + kb + t + 4];
            }
#pragma unroll
            for (int mt = 0; mt < 4; ++mt)
#pragma unroll
                for (int nt = 0; nt < 4; ++nt)
                    mma_tf32(acc[mt][nt],
                             af[mt][0], af[mt][1], af[mt][2], af[mt][3],
                             bf[nt][0], bf[nt][1]);
        }
    }

#pragma unroll
    for (int mt = 0; mt < 4; ++mt) {
        int row = m0 + wm + (mt << 4) + g;
#pragma unroll
        for (int nt = 0; nt < 4; ++nt) {
            int col = n0 + wn + (nt << 3) + (t << 1);
            float2 v0; v0.x = acc[mt][nt][0]; v0.y = acc[mt][nt][1];
            float2 v1; v1.x = acc[mt][nt][2]; v1.y = acc[mt][nt][3];
            *(float2*)(C + (size_t)row * N + col)       = v0;
            *(float2*)(C + (size_t)(row + 8) * N + col) = v1;
        }
    }
}

/* ---------------- per-head RMSNorm + RoPE + scatter (tf32-rounded out) ----- */
__global__ void norm_rope(
    const float* __restrict__ qkv, const int* __restrict__ pos,
    const float* __restrict__ qw, const float* __restrict__ kw,
    float* __restrict__ qo, float* __restrict__ ko, float* __restrict__ vo)
{
    const int slot = blockIdx.x, s = blockIdx.y, b = blockIdx.z;
    const int d = threadIdx.x;
    const size_t token = (size_t)b * SS + s;
    float x = qkv[token * QKV_O + (size_t)slot * HD + d];

    if (slot >= 36) {
        vo[(((size_t)b * NKV + (slot - 36)) * SS + s) * HD + d] = rtf(x);
        return;
    }

    __shared__ float red[4];
    __shared__ float xs[HD];
    __shared__ float rstd;

    float ssq = x * x;
#pragma unroll
    for (int o = 16; o; o >>= 1) ssq += __shfl_xor_sync(0xffffffffu, ssq, o);
    if ((d & 31) == 0) red[d >> 5] = ssq;
    __syncthreads();
    if (d == 0) rstd = rsqrtf((red[0] + red[1] + red[2] + red[3]) * (1.0f / HD) + 1e-6f);
    __syncthreads();

    float w = (slot < 32) ? qw[d] : kw[d];
    float xn = x * rstd * w;
    xs[d] = xn;
    __syncthreads();

    int p = pos[token];
    int j = d & 63;
    float invf = expf((float)j * (-13.815510557964274f / 64.0f));
    float ang = (float)p * invf;
    float sn, cs;
    sincosf(ang, &sn, &cs);
    float out = (d < 64) ? (xn * cs - xs[d + 64] * sn)
                         : (xn * cs + xs[d - 64] * sn);

    if (slot < 32) qo[(((size_t)b * NH + slot) * SS + s) * HD + d] = rtf(out * SCALE);
    else           ko[(((size_t)b * NKV + (slot - 32)) * SS + s) * HD + d] = rtf(out);
}

/* ---------------- flash attention v3: 64x64, 4 warps, 2 CTA/SM -------------
   Q fragments in registers (loaded once); K/V staged by cp.async per tile,
   already tf32-valued (no cvt anywhere); dedicated per-warp P smem.
   Smem words: Q 8192 (swz (r&7)<<2), K 8192 (swz (r&7)<<2),
   V 8192 (swz (r&3)<<3), P 4x1024 (swz g<<2). 114688 B -> 2 CTA/SM. */
#define FBQ  64
#define FBK  64
#define QW2  8192
#define KW2  8192
#define VW2  8192
#define PW2  4096
#define F6_SMEM ((QW2 + KW2 + VW2 + PW2) * 4)   /* 114688 */

__global__ __launch_bounds__(128, 2) void flash_tc(
    const float* __restrict__ Qb, const float* __restrict__ Kb,
    const float* __restrict__ Vb, float* __restrict__ Ob)
{
    extern __shared__ uint32_t su[];
    uint32_t* Qs = su;
    uint32_t* Ks = su + QW2;
    uint32_t* Vs = su + QW2 + KW2;
    uint32_t* Ps = su + QW2 + KW2 + VW2;

    const int tid = threadIdx.x;
    const int lane = tid & 31, w = tid >> 5;
    const int g = lane >> 2, t = lane & 3;
    const int qt = (gridDim.x - 1) - blockIdx.x;   /* heaviest first */
    const int h = blockIdx.y, b = blockIdx.z;
    const int q0 = qt * FBQ;
    const int kh = h >> 3;

    const float* Qg  = Qb + (((size_t)b * NH + h) * SS + q0) * HD;
    const float* Kg0 = Kb + ((size_t)b * NKV + kh) * SS * HD;
    const float* Vg0 = Vb + ((size_t)b * NKV + kh) * SS * HD;

    /* prologue: stage Q (pre-scaled, pre-rounded) via cp.async */
#pragma unroll
    for (int i = 0; i < 16; ++i) {
        int f = tid + (i << 7);
        int r = f >> 5, c4 = (f & 31) << 2;
        cp16(Qs + r * 128 + (c4 ^ ((r & 7) << 2)), Qg + (size_t)r * HD + c4);
    }
    cp_commit(); cp_wait0(); __syncthreads();

    /* Q fragments -> registers (reused every tile) */
    const int swg = g << 2;
    uint32_t qa0[16], qa1[16], qa2[16], qa3[16];
    {
        const int r0 = (w * 16 + g) * 128, r1 = (w * 16 + g + 8) * 128;
#pragma unroll
        for (int ks = 0; ks < 16; ++ks) {
            int kb = ks << 3;
            int cA = (kb + t) ^ swg, cB = (kb + t + 4) ^ swg;
            qa0[ks] = Qs[r0 + cA]; qa1[ks] = Qs[r1 + cA];
            qa2[ks] = Qs[r0 + cB]; qa3[ks] = Qs[r1 + cB];
        }
    }

    float o[16][4];
#pragma unroll
    for (int dt = 0; dt < 16; ++dt)
#pragma unroll
        for (int i = 0; i < 4; ++i) o[dt][i] = 0.0f;
    float mr0 = -1e30f, mr1 = -1e30f, lr0 = 0.0f, lr1 = 0.0f;

    uint32_t* Pw = Ps + w * 1024;
    const int qrow0 = q0 + w * 16 + g;

    const int ntiles = qt + 1;
    for (int tt = 0; tt < ntiles; ++tt) {
        __syncthreads();   /* all warps done with previous K/V/P */
        const float* Kg = Kg0 + (size_t)tt * FBK * HD;
        const float* Vg = Vg0 + (size_t)tt * FBK * HD;
#pragma unroll
        for (int i = 0; i < 16; ++i) {
            int f = tid + (i << 7);
            int r = f >> 5, c4 = (f & 31) << 2;
            cp16(Ks + r * 128 + (c4 ^ ((r & 7) << 2)), Kg + (size_t)r * HD + c4);
            cp16(Vs + r * 128 + (c4 ^ ((r & 3) << 3)), Vg + (size_t)r * HD + c4);
        }
        cp_commit(); cp_wait0();
        __syncthreads();   /* K/V visible to all threads */

        /* S = Q K^T */
        float sc[8][4];
#pragma unroll
        for (int nt = 0; nt < 8; ++nt)
#pragma unroll
            for (int i = 0; i < 4; ++i) sc[nt][i] = 0.0f;

#pragma unroll
        for (int ks = 0; ks < 16; ++ks) {
            const int kb = ks << 3;
            const int cA = (kb + t) ^ swg;
            const int cB = (kb + t + 4) ^ swg;
#pragma unroll
            for (int nt = 0; nt < 8; ++nt) {
                uint32_t b0 = Ks[(nt * 8 + g) * 128 + cA];
                uint32_t b1 = Ks[(nt * 8 + g) * 128 + cB];
                mma_tf32(sc[nt], qa0[ks], qa1[ks], qa2[ks], qa3[ks], b0, b1);
            }
        }

        /* causal mask: diagonal (last) tile only */
        if (tt == ntiles - 1) {
            const int k0g = tt * FBK + 2 * t;
#pragma unroll
            for (int nt = 0; nt < 8; ++nt) {
                int kc = k0g + nt * 8;
                if (kc     > qrow0)     sc[nt][0] = -1e30f;
                if (kc + 1 > qrow0)     sc[nt][1] = -1e30f;
                if (kc     > qrow0 + 8) sc[nt][2] = -1e30f;
                if (kc + 1 > qrow0 + 8) sc[nt][3] = -1e30f;
            }
        }

        /* online softmax (rows qrow0, qrow0+8); quad shfl reduce */
        float m0 = -1e30f, m1 = -1e30f;
#pragma unroll
        for (int nt = 0; nt < 8; ++nt) {
            m0 = fmaxf(m0, fmaxf(sc[nt][0], sc[nt][1]));
            m1 = fmaxf(m1, fmaxf(sc[nt][2], sc[nt][3]));
        }
        m0 = fmaxf(m0, __shfl_xor_sync(0xffffffffu, m0, 1));
        m0 = fmaxf(m0, __shfl_xor_sync(0xffffffffu, m0, 2));
        m1 = fmaxf(m1, __shfl_xor_sync(0xffffffffu, m1, 1));
        m1 = fmaxf(m1, __shfl_xor_sync(0xffffffffu, m1, 2));
        float mn0 = fmaxf(mr0, m0), mn1 = fmaxf(mr1, m1);
        float a0r = __expf(mr0 - mn0), a1r = __expf(mr1 - mn1);
        float s0 = 0.0f, s1 = 0.0f;
#pragma unroll
        for (int nt = 0; nt < 8; ++nt) {
            sc[nt][0] = __expf(sc[nt][0] - mn0); s0 += sc[nt][0];
            sc[nt][1] = __expf(sc[nt][1] - mn0); s0 += sc[nt][1];
            sc[nt][2] = __expf(sc[nt][2] - mn1); s1 += sc[nt][2];
            sc[nt][3] = __expf(sc[nt][3] - mn1); s1 += sc[nt][3];
        }
        s0 += __shfl_xor_sync(0xffffffffu, s0, 1);
        s0 += __shfl_xor_sync(0xffffffffu, s0, 2);
        s1 += __shfl_xor_sync(0xffffffffu, s1, 1);
        s1 += __shfl_xor_sync(0xffffffffu, s1, 2);
        lr0 = lr0 * a0r + s0; mr0 = mn0;
        lr1 = lr1 * a1r + s1; mr1 = mn1;
#pragma unroll
        for (int dt = 0; dt < 16; ++dt) {
            o[dt][0] *= a0r; o[dt][1] *= a0r;
            o[dt][2] *= a1r; o[dt][3] *= a1r;
        }

        /* P -> per-warp smem (tf32, 16x64 swizzled) */
#pragma unroll
        for (int nt = 0; nt < 8; ++nt) {
            int c = nt * 8 + 2 * t;
            int cw = c ^ swg;
            Pw[g * 64 + cw]           = f2tf32(sc[nt][0]);
            Pw[g * 64 + cw + 1]       = f2tf32(sc[nt][1]);
            Pw[(g + 8) * 64 + cw]     = f2tf32(sc[nt][2]);
            Pw[(g + 8) * 64 + cw + 1] = f2tf32(sc[nt][3]);
        }
        __syncwarp();

        /* O += P V */
#pragma unroll
        for (int ks = 0; ks < 8; ++ks) {
            const int kb = ks << 3;
            const int cA = (kb + t) ^ swg;
            const int cB = (kb + t + 4) ^ swg;
            uint32_t a0 = Pw[g * 64 + cA];
            uint32_t a1 = Pw[(g + 8) * 64 + cA];
            uint32_t a2 = Pw[g * 64 + cB];
            uint32_t a3 = Pw[(g + 8) * 64 + cB];
            const int vr0 = (kb + t) * 128;
            const int vr1 = (kb + t + 4) * 128;
            const int vsw = t << 3;
#pragma unroll
            for (int dt = 0; dt < 16; ++dt) {
                int vc = (dt * 8 + g) ^ vsw;
                uint32_t b0 = Vs[vr0 + vc];
                uint32_t b1 = Vs[vr1 + vc];
                mma_tf32(o[dt], a0, a1, a2, a3, b0, b1);
            }
        }
    }

    /* epilogue -> [b][s][h][d], tf32-rounded for the O-proj GEMM */
    const float inv0 = 1.0f / lr0, inv1 = 1.0f / lr1;
    const size_t base0 = (((size_t)b * SS + qrow0) * NH + h) * HD;
    const size_t base1 = (((size_t)b * SS + qrow0 + 8) * NH + h) * HD;
#pragma unroll
    for (int dt = 0; dt < 16; ++dt) {
        int col = dt * 8 + 2 * t;
        float2 v0; v0.x = rtf(o[dt][0] * inv0); v0.y = rtf(o[dt][1] * inv0);
        float2 v1; v1.x = rtf(o[dt][2] * inv1); v1.y = rtf(o[dt][3] * inv1);
        *(float2*)(Ob + base0 + col) = v0;
        *(float2*)(Ob + base1 + col) = v1;
    }
}

/* ---------------- launch ---------------- */
extern "C" void kernel_launch(void* const* d_in, const int* in_sizes, int n_in,
                              void* d_out, int out_size)
{
    const float* hidden    = (const float*)d_in[0];
    const int*   positions = (const int*)d_in[1];
    const float* w_qkv     = (const float*)d_in[2];
    const float* w_o       = (const float*)d_in[3];
    const float* qw        = (const float*)d_in[4];
    const float* kw        = (const float*)d_in[5];
    float* out = (float*)d_out;

    float *qkv, *qb, *kb, *vb, *ab, *hid, *wq, *wo;
    cudaGetSymbolAddress((void**)&qkv, g_qkv);
    cudaGetSymbolAddress((void**)&qb,  g_q);
    cudaGetSymbolAddress((void**)&kb,  g_k);
    cudaGetSymbolAddress((void**)&vb,  g_v);
    cudaGetSymbolAddress((void**)&ab,  g_attn);
    cudaGetSymbolAddress((void**)&hid, g_hid);
    cudaGetSymbolAddress((void**)&wq,  g_wq);
    cudaGetSymbolAddress((void**)&wo,  g_wo);

    cudaFuncSetAttribute(gemm_tf32, cudaFuncAttributeMaxDynamicSharedMemorySize, G_SMEM);
    cudaFuncSetAttribute(flash_tc, cudaFuncAttributeMaxDynamicSharedMemorySize, F6_SMEM);

    /* 0. pre-round inputs to tf32 */
    {
        int n4h = MTOK * HIDDEN / 4;
        round_tf32<<<n4h / 256, 256>>>((const float4*)hidden, (float4*)hid, n4h);
        int n4q = QKV_O * HIDDEN / 4;
        round_tf32<<<n4q / 256, 256>>>((const float4*)w_qkv, (float4*)wq, n4q);
        int n4o = HIDDEN * NH * HD / 4;
        round_tf32<<<n4o / 256, 256>>>((const float4*)w_o, (float4*)wo, n4o);
    }

    /* 1. QKV projection */
    gemm_tf32<<<dim3(QKV_O / 128, MTOK / 128), 256, G_SMEM>>>(hid, wq, qkv, MTOK, QKV_O, HIDDEN);

    /* 2. RMSNorm + RoPE + scatter (tf32-rounded, q pre-scaled) */
    norm_rope<<<dim3(40, SS, BB), 128>>>(qkv, positions, qw, kw, qb, kb, vb);

    /* 3. causal flash attention */
    flash_tc<<<dim3(SS / FBQ, NH, BB), 128, F6_SMEM>>>(qb, kb, vb, ab);

    /* 4. O projection */
    gemm_tf32<<<dim3(HIDDEN / 128, MTOK / 128), 256, G_SMEM>>>(ab, wo, out, MTOK, HIDDEN, NH * HD);
}